// round 3
// baseline (speedup 1.0000x reference)
#include <cuda_runtime.h>
#include <cuda_bf16.h>

// Problem constants (fixed by setup_inputs)
#define BATCH 4
#define SEQ   2048
#define CDIM  1024
#define NHEAD 16
#define HDIM  64
#define MROWS (BATCH * SEQ)   // 8192

// Scratch (allocation-free: __device__ globals)
__device__ float g_Q[BATCH * NHEAD * SEQ * HDIM];
__device__ float g_K[BATCH * NHEAD * SEQ * HDIM];
__device__ float g_V[BATCH * NHEAD * SEQ * HDIM];
__device__ float g_Y[BATCH * SEQ * CDIM];

// ---------------------------------------------------------------------------
// SGEMM: out = A[M,K] @ W[N,K]^T + bias   (torch Linear convention)
// BM=BN=128, BK=8, 256 threads, 8x8 register tile per thread.
// mode 0: write split-heads layout [B,H,T,D]; mode 1: plain [M,N].
// ---------------------------------------------------------------------------
__global__ __launch_bounds__(256)
void sgemm128(const float* __restrict__ A, const float* __restrict__ W,
              const float* __restrict__ bias, float* __restrict__ out, int mode)
{
    const int K = CDIM;
    const int N = CDIM;
    __shared__ float As[8][128];
    __shared__ float Bs[8][128];

    const int tid  = threadIdx.x;
    const int bm   = blockIdx.y * 128;
    const int bn   = blockIdx.x * 128;

    const int lRow = tid >> 1;            // 0..127
    const int lCol = (tid & 1) << 2;      // 0 or 4

    const float* Ag = A + (size_t)(bm + lRow) * K + lCol;
    const float* Wg = W + (size_t)(bn + lRow) * K + lCol;

    const int tr = tid >> 4;              // 0..15
    const int tc = tid & 15;              // 0..15

    float acc[8][8];
#pragma unroll
    for (int i = 0; i < 8; i++)
#pragma unroll
        for (int j = 0; j < 8; j++) acc[i][j] = 0.0f;

    for (int k0 = 0; k0 < K; k0 += 8) {
        float4 av = *(const float4*)(Ag + k0);
        float4 wv = *(const float4*)(Wg + k0);
        As[lCol + 0][lRow] = av.x;
        As[lCol + 1][lRow] = av.y;
        As[lCol + 2][lRow] = av.z;
        As[lCol + 3][lRow] = av.w;
        Bs[lCol + 0][lRow] = wv.x;
        Bs[lCol + 1][lRow] = wv.y;
        Bs[lCol + 2][lRow] = wv.z;
        Bs[lCol + 3][lRow] = wv.w;
        __syncthreads();

#pragma unroll
        for (int k = 0; k < 8; k++) {
            float ra[8], rb[8];
#pragma unroll
            for (int i = 0; i < 8; i++) ra[i] = As[k][tr * 8 + i];
#pragma unroll
            for (int j = 0; j < 8; j++) rb[j] = Bs[k][tc * 8 + j];
#pragma unroll
            for (int i = 0; i < 8; i++)
#pragma unroll
                for (int j = 0; j < 8; j++)
                    acc[i][j] = fmaf(ra[i], rb[j], acc[i][j]);
        }
        __syncthreads();
    }

#pragma unroll
    for (int i = 0; i < 8; i++) {
        const int row = bm + tr * 8 + i;
#pragma unroll
        for (int j = 0; j < 8; j++) {
            const int col = bn + tc * 8 + j;
            const float v = acc[i][j] + bias[col];
            if (mode == 0) {
                // split heads: [B,H,T,D]
                const int b = row >> 11;         // / SEQ
                const int t = row & (SEQ - 1);
                const int h = col >> 6;          // / HDIM
                const int d = col & (HDIM - 1);
                out[(((size_t)(b * NHEAD + h) * SEQ) + t) * HDIM + d] = v;
            } else {
                out[(size_t)row * N + col] = v;
            }
        }
    }
}

// ---------------------------------------------------------------------------
// Flash attention (causal), fp32. One block per (q-tile, head, batch).
// BQ = BKV = 64, D = 64. 256 threads as 16x16, each owning 4x4 of S and
// 4x4 of O. Online softmax state (m, l) per row in smem; row reductions via
// 16-lane shfl butterflies (row ownership never crosses a 16-lane group).
// ---------------------------------------------------------------------------
#define QS(d, r)  smQ[(d) * 65 + (r)]
#define KS(d, r)  smK[(d) * 65 + (r)]
#define PS(c, r)  smP[(c) * 65 + (r)]
#define VS(j, d)  smV[(j) * 68 + (d)]
#define ATT_SMEM_FLOATS (64*65*3 + 64*68 + 128)
#define ATT_SMEM_BYTES  (ATT_SMEM_FLOATS * 4)

__global__ __launch_bounds__(256)
void flash_attn_kernel()
{
    extern __shared__ float sm[];
    float* smQ = sm;
    float* smK = smQ + 64 * 65;
    float* smP = smK + 64 * 65;
    float* smV = smP + 64 * 65;
    float* mrow = smV + 64 * 68;
    float* lrow = mrow + 64;

    const int qt = blockIdx.x;     // 0..31
    const int h  = blockIdx.y;
    const int b  = blockIdx.z;
    const int tid = threadIdx.x;
    const int ty = tid >> 4;       // 0..15 (row group)
    const int tx = tid & 15;       // 0..15 (col group)

    const size_t headBase = ((size_t)(b * NHEAD + h)) * SEQ * HDIM;
    const float* Qg = g_Q + headBase;
    const float* Kg = g_K + headBase;
    const float* Vg = g_V + headBase;

    // Load Q tile (transposed into [d][row]) once.
    {
        const int r0 = tid >> 4;            // 0..15
        const int d0 = (tid & 15) * 4;
#pragma unroll
        for (int r = 0; r < 4; r++) {
            const int row = r0 + r * 16;
            float4 v = *(const float4*)(Qg + (size_t)(qt * 64 + row) * HDIM + d0);
            QS(d0 + 0, row) = v.x;
            QS(d0 + 1, row) = v.y;
            QS(d0 + 2, row) = v.z;
            QS(d0 + 3, row) = v.w;
        }
    }
    if (tid < 64) { mrow[tid] = -1e30f; lrow[tid] = 0.0f; }

    float o[4][4];
#pragma unroll
    for (int i = 0; i < 4; i++)
#pragma unroll
        for (int j = 0; j < 4; j++) o[i][j] = 0.0f;

    const float scale = 0.125f; // 1/sqrt(64)

    for (int jt = 0; jt <= qt; jt++) {
        __syncthreads();   // prior PV reads of smV/smP done before overwrite

        // Load K tile (transposed [d][col]) and V tile ([j][d]).
        {
            const int r0 = tid >> 4;
            const int d0 = (tid & 15) * 4;
#pragma unroll
            for (int r = 0; r < 4; r++) {
                const int row = r0 + r * 16;
                float4 kv = *(const float4*)(Kg + (size_t)(jt * 64 + row) * HDIM + d0);
                KS(d0 + 0, row) = kv.x;
                KS(d0 + 1, row) = kv.y;
                KS(d0 + 2, row) = kv.z;
                KS(d0 + 3, row) = kv.w;
                float4 vv = *(const float4*)(Vg + (size_t)(jt * 64 + row) * HDIM + d0);
                *(float4*)&VS(row, d0) = vv;
            }
        }
        __syncthreads();

        // S = (Q K^T) * scale, 4x4 per thread
        float s[4][4];
#pragma unroll
        for (int i = 0; i < 4; i++)
#pragma unroll
            for (int j = 0; j < 4; j++) s[i][j] = 0.0f;

#pragma unroll 8
        for (int d = 0; d < 64; d++) {
            float qa[4], ka[4];
#pragma unroll
            for (int i = 0; i < 4; i++) qa[i] = QS(d, ty * 4 + i);
#pragma unroll
            for (int j = 0; j < 4; j++) ka[j] = KS(d, tx * 4 + j);
#pragma unroll
            for (int i = 0; i < 4; i++)
#pragma unroll
                for (int j = 0; j < 4; j++)
                    s[i][j] = fmaf(qa[i], ka[j], s[i][j]);
        }

#pragma unroll
        for (int i = 0; i < 4; i++)
#pragma unroll
            for (int j = 0; j < 4; j++) s[i][j] *= scale;

        // Causal mask on the diagonal tile
        if (jt == qt) {
#pragma unroll
            for (int i = 0; i < 4; i++) {
                const int row = ty * 4 + i;
#pragma unroll
                for (int j = 0; j < 4; j++) {
                    const int col = tx * 4 + j;
                    if (col > row) s[i][j] = -1e30f;
                }
            }
        }

        // Online softmax per row (rows ty*4+i, spread over 16 tx lanes)
        float p[4][4];
        float corr[4];
#pragma unroll
        for (int i = 0; i < 4; i++) {
            float rm = fmaxf(fmaxf(s[i][0], s[i][1]), fmaxf(s[i][2], s[i][3]));
#pragma unroll
            for (int off = 1; off < 16; off <<= 1)
                rm = fmaxf(rm, __shfl_xor_sync(0xffffffffu, rm, off));

            const int row = ty * 4 + i;
            const float mo = mrow[row];
            const float mn = fmaxf(mo, rm);
            corr[i] = __expf(mo - mn);

            float sum = 0.0f;
#pragma unroll
            for (int j = 0; j < 4; j++) {
                const float pv = __expf(s[i][j] - mn);
                p[i][j] = pv;
                sum += pv;
            }
#pragma unroll
            for (int off = 1; off < 16; off <<= 1)
                sum += __shfl_xor_sync(0xffffffffu, sum, off);

            if (tx == 0) {
                mrow[row] = mn;
                lrow[row] = lrow[row] * corr[i] + sum;
            }
        }

        // Rescale O, stash P (transposed [col][row]) for the PV GEMM
#pragma unroll
        for (int i = 0; i < 4; i++)
#pragma unroll
            for (int j = 0; j < 4; j++) o[i][j] *= corr[i];

#pragma unroll
        for (int i = 0; i < 4; i++)
#pragma unroll
            for (int j = 0; j < 4; j++)
                PS(tx * 4 + j, ty * 4 + i) = p[i][j];

        __syncthreads();

        // O += P @ V : O[row][d], d tiled by tx
#pragma unroll 4
        for (int j = 0; j < 64; j++) {
            float pb[4];
#pragma unroll
            for (int i = 0; i < 4; i++) pb[i] = PS(j, ty * 4 + i);
            float4 vv = *(const float4*)&VS(j, tx * 4);
#pragma unroll
            for (int i = 0; i < 4; i++) {
                o[i][0] = fmaf(pb[i], vv.x, o[i][0]);
                o[i][1] = fmaf(pb[i], vv.y, o[i][1]);
                o[i][2] = fmaf(pb[i], vv.z, o[i][2]);
                o[i][3] = fmaf(pb[i], vv.w, o[i][3]);
            }
        }
    }

    // Epilogue: divide by l, write Y in [B,T,C] layout (merge heads)
#pragma unroll
    for (int i = 0; i < 4; i++) {
        const int row = ty * 4 + i;
        const float inv = 1.0f / lrow[row];
        const int t = qt * 64 + row;
        float4 ov;
        ov.x = o[i][0] * inv;
        ov.y = o[i][1] * inv;
        ov.z = o[i][2] * inv;
        ov.w = o[i][3] * inv;
        *(float4*)&g_Y[((size_t)b * SEQ + t) * CDIM + h * HDIM + tx * 4] = ov;
    }
}

// ---------------------------------------------------------------------------
// Launch
// ---------------------------------------------------------------------------
extern "C" void kernel_launch(void* const* d_in, const int* in_sizes, int n_in,
                              void* d_out, int out_size)
{
    const float* x  = (const float*)d_in[0];
    const float* Wq = (const float*)d_in[1];
    const float* bq = (const float*)d_in[2];
    const float* Wk = (const float*)d_in[3];
    const float* bk = (const float*)d_in[4];
    const float* Wv = (const float*)d_in[5];
    const float* bv = (const float*)d_in[6];
    const float* Wp = (const float*)d_in[7];
    const float* bp = (const float*)d_in[8];

    float *Qp, *Kp, *Vp, *Yp;
    cudaGetSymbolAddress((void**)&Qp, g_Q);
    cudaGetSymbolAddress((void**)&Kp, g_K);
    cudaGetSymbolAddress((void**)&Vp, g_V);
    cudaGetSymbolAddress((void**)&Yp, g_Y);

    cudaFuncSetAttribute(flash_attn_kernel,
                         cudaFuncAttributeMaxDynamicSharedMemorySize,
                         ATT_SMEM_BYTES);

    dim3 gemmGrid(CDIM / 128, MROWS / 128);   // (8, 64)
    sgemm128<<<gemmGrid, 256>>>(x, Wq, bq, Qp, 0);
    sgemm128<<<gemmGrid, 256>>>(x, Wk, bk, Kp, 0);
    sgemm128<<<gemmGrid, 256>>>(x, Wv, bv, Vp, 0);

    dim3 attnGrid(SEQ / 64, NHEAD, BATCH);    // (32, 16, 4)
    flash_attn_kernel<<<attnGrid, 256, ATT_SMEM_BYTES>>>();

    sgemm128<<<gemmGrid, 256>>>(Yp, Wp, bp, (float*)d_out, 1);
}

// round 4
// speedup vs baseline: 1.6151x; 1.6151x over previous
#include <cuda_runtime.h>
#include <cuda_bf16.h>
#include <cstdint>

// Problem constants (fixed by setup_inputs)
#define BATCH 4
#define SEQ   2048
#define CDIM  1024
#define NHEAD 16
#define HDIM  64
#define MROWS (BATCH * SEQ)   // 8192
#define K3    (3 * CDIM)      // 3072 : [hi | hi | lo] x [hi | lo | hi]

// Scratch (allocation-free: __device__ globals)
__device__ float g_Q[BATCH * NHEAD * SEQ * HDIM];
__device__ float g_K[BATCH * NHEAD * SEQ * HDIM];
__device__ float g_V[BATCH * NHEAD * SEQ * HDIM];
__device__ float g_Y[BATCH * SEQ * CDIM];

__device__ __nv_bfloat16 g_A3[MROWS * K3];   // split-expanded x
__device__ __nv_bfloat16 g_Y3[MROWS * K3];   // split-expanded attention output
__device__ __nv_bfloat16 g_W3q[CDIM * K3];
__device__ __nv_bfloat16 g_W3k[CDIM * K3];
__device__ __nv_bfloat16 g_W3v[CDIM * K3];
__device__ __nv_bfloat16 g_W3p[CDIM * K3];

// ---------------------------------------------------------------------------
// Split-convert: fp32 [rows,1024] -> bf16 [rows,3072].
// modeA=1: cols [0,1K)=hi, [1K,2K)=hi, [2K,3K)=lo   (activations)
// modeA=0: cols [0,1K)=hi, [1K,2K)=lo, [2K,3K)=hi   (weights)
// A'@W'^T = hi*hi + hi*lo + lo*hi  (3-term compensated bf16 product)
// ---------------------------------------------------------------------------
__global__ __launch_bounds__(256)
void cvt_split3(const float* __restrict__ src, __nv_bfloat16* __restrict__ dst,
                int total, int modeA)
{
    int idx = blockIdx.x * 256 + threadIdx.x;
    if (idx >= total) return;
    int r = idx >> 10;
    int k = idx & 1023;
    float a = src[idx];
    __nv_bfloat16 hi = __float2bfloat16(a);
    __nv_bfloat16 lo = __float2bfloat16(a - __bfloat162float(hi));
    __nv_bfloat16* row = dst + (size_t)r * K3;
    if (modeA) {
        row[k]        = hi;
        row[k + 1024] = hi;
        row[k + 2048] = lo;
    } else {
        row[k]        = hi;
        row[k + 1024] = lo;
        row[k + 2048] = hi;
    }
}

// ---------------------------------------------------------------------------
// bf16 tensor-core GEMM: out[M,1024] = A3[M,3072] @ W3[1024,3072]^T + bias.
// 128x128 block tile, BK=32, 256 threads = 8 warps (2 m x 4 n), warp tile
// 64x32, mma.sync.m16n8k16 bf16->fp32. Smem rows padded to 40 bf16 (20 banks)
// so fragment LDS is conflict-free. Global loads staged through registers.
// mode 0: write split-heads [B,H,T,D]; mode 1: plain [M,N].
// ---------------------------------------------------------------------------
__device__ __forceinline__ void mma16816(float* d, const uint32_t* a, const uint32_t* b)
{
    asm volatile(
        "mma.sync.aligned.m16n8k16.row.col.f32.bf16.bf16.f32 "
        "{%0,%1,%2,%3}, {%4,%5,%6,%7}, {%8,%9}, {%0,%1,%2,%3};"
        : "+f"(d[0]), "+f"(d[1]), "+f"(d[2]), "+f"(d[3])
        : "r"(a[0]), "r"(a[1]), "r"(a[2]), "r"(a[3]),
          "r"(b[0]), "r"(b[1]));
}

#define SMPAD 40   // padded row length in bf16 elements (80B = 20 banks)

__global__ __launch_bounds__(256)
void gemm_bf16_mma(const __nv_bfloat16* __restrict__ A,
                   const __nv_bfloat16* __restrict__ W,
                   const float* __restrict__ bias,
                   float* __restrict__ out, int mode)
{
    __shared__ __nv_bfloat16 As[128][SMPAD];
    __shared__ __nv_bfloat16 Ws[128][SMPAD];

    const int tid  = threadIdx.x;
    const int bm   = blockIdx.y * 128;
    const int bn   = blockIdx.x * 128;
    const int warp = tid >> 5;
    const int lane = tid & 31;
    const int wm   = (warp >> 2) * 64;   // warp m-offset within tile
    const int wn   = (warp & 3) * 32;    // warp n-offset within tile
    const int g    = lane >> 2;          // 0..7
    const int c    = lane & 3;           // 0..3

    // Global-load mapping: 512 uint4 per 128x32 tile; thread handles u=tid, tid+256.
    const int r0 = tid >> 2,         q0 = tid & 3;          // u = tid
    const int r1 = (tid + 256) >> 2, q1 = (tid + 256) & 3;  // u = tid+256

    const __nv_bfloat16* Ag0 = A + (size_t)(bm + r0) * K3 + q0 * 8;
    const __nv_bfloat16* Ag1 = A + (size_t)(bm + r1) * K3 + q1 * 8;
    const __nv_bfloat16* Wg0 = W + (size_t)(bn + r0) * K3 + q0 * 8;
    const __nv_bfloat16* Wg1 = W + (size_t)(bn + r1) * K3 + q1 * 8;

    float acc[4][4][4];
#pragma unroll
    for (int i = 0; i < 4; i++)
#pragma unroll
        for (int j = 0; j < 4; j++)
#pragma unroll
            for (int e = 0; e < 4; e++) acc[i][j][e] = 0.0f;

    uint4 pa0, pa1, pw0, pw1;
    pa0 = *(const uint4*)(Ag0);
    pa1 = *(const uint4*)(Ag1);
    pw0 = *(const uint4*)(Wg0);
    pw1 = *(const uint4*)(Wg1);

    for (int k0 = 0; k0 < K3; k0 += 32) {
        // stage registers -> smem
        *(uint4*)&As[r0][q0 * 8] = pa0;
        *(uint4*)&As[r1][q1 * 8] = pa1;
        *(uint4*)&Ws[r0][q0 * 8] = pw0;
        *(uint4*)&Ws[r1][q1 * 8] = pw1;
        __syncthreads();

        // prefetch next tile (latency overlapped with mma work below)
        if (k0 + 32 < K3) {
            pa0 = *(const uint4*)(Ag0 + k0 + 32);
            pa1 = *(const uint4*)(Ag1 + k0 + 32);
            pw0 = *(const uint4*)(Wg0 + k0 + 32);
            pw1 = *(const uint4*)(Wg1 + k0 + 32);
        }

#pragma unroll
        for (int kk = 0; kk < 2; kk++) {
            const int kb = kk * 16;
            uint32_t af[4][4];
#pragma unroll
            for (int mf = 0; mf < 4; mf++) {
                const int mr = wm + mf * 16 + g;
                af[mf][0] = *(const uint32_t*)&As[mr    ][kb + 2 * c];
                af[mf][1] = *(const uint32_t*)&As[mr + 8][kb + 2 * c];
                af[mf][2] = *(const uint32_t*)&As[mr    ][kb + 2 * c + 8];
                af[mf][3] = *(const uint32_t*)&As[mr + 8][kb + 2 * c + 8];
            }
            uint32_t bf[4][2];
#pragma unroll
            for (int nf = 0; nf < 4; nf++) {
                const int nr = wn + nf * 8 + g;
                bf[nf][0] = *(const uint32_t*)&Ws[nr][kb + 2 * c];
                bf[nf][1] = *(const uint32_t*)&Ws[nr][kb + 2 * c + 8];
            }
#pragma unroll
            for (int mf = 0; mf < 4; mf++)
#pragma unroll
                for (int nf = 0; nf < 4; nf++)
                    mma16816(acc[mf][nf], af[mf], bf[nf]);
        }
        __syncthreads();
    }

    // Epilogue: c0=(g,2c) c1=(g,2c+1) c2=(g+8,2c) c3=(g+8,2c+1) per 16x8 frag
#pragma unroll
    for (int nf = 0; nf < 4; nf++) {
        const int col = bn + wn + nf * 8 + 2 * c;
        const float b0 = bias[col];
        const float b1 = bias[col + 1];
#pragma unroll
        for (int mf = 0; mf < 4; mf++) {
            const int row = bm + wm + mf * 16 + g;
            const float v00 = acc[mf][nf][0] + b0;
            const float v01 = acc[mf][nf][1] + b1;
            const float v10 = acc[mf][nf][2] + b0;
            const float v11 = acc[mf][nf][3] + b1;
            if (mode == 0) {
                // split heads: [B,H,T,D]
                const int h = col >> 6;
                const int d = col & (HDIM - 1);
                const int b_  = row >> 11;
                const int t0  = row & (SEQ - 1);
                const int b2  = (row + 8) >> 11;
                const int t1  = (row + 8) & (SEQ - 1);
                float* o0 = out + (((size_t)(b_ * NHEAD + h) * SEQ) + t0) * HDIM + d;
                float* o1 = out + (((size_t)(b2 * NHEAD + h) * SEQ) + t1) * HDIM + d;
                o0[0] = v00; o0[1] = v01;
                o1[0] = v10; o1[1] = v11;
            } else {
                *(float2*)(out + (size_t)row * CDIM + col)       = make_float2(v00, v01);
                *(float2*)(out + (size_t)(row + 8) * CDIM + col) = make_float2(v10, v11);
            }
        }
    }
}

// ---------------------------------------------------------------------------
// Flash attention (causal), fp32 — unchanged from the passing baseline.
// ---------------------------------------------------------------------------
#define QS(d, r)  smQ[(d) * 65 + (r)]
#define KS(d, r)  smK[(d) * 65 + (r)]
#define PS(c, r)  smP[(c) * 65 + (r)]
#define VS(j, d)  smV[(j) * 68 + (d)]
#define ATT_SMEM_FLOATS (64*65*3 + 64*68 + 128)
#define ATT_SMEM_BYTES  (ATT_SMEM_FLOATS * 4)

__global__ __launch_bounds__(256)
void flash_attn_kernel()
{
    extern __shared__ float sm[];
    float* smQ = sm;
    float* smK = smQ + 64 * 65;
    float* smP = smK + 64 * 65;
    float* smV = smP + 64 * 65;
    float* mrow = smV + 64 * 68;
    float* lrow = mrow + 64;

    const int qt = blockIdx.x;
    const int h  = blockIdx.y;
    const int b  = blockIdx.z;
    const int tid = threadIdx.x;
    const int ty = tid >> 4;
    const int tx = tid & 15;

    const size_t headBase = ((size_t)(b * NHEAD + h)) * SEQ * HDIM;
    const float* Qg = g_Q + headBase;
    const float* Kg = g_K + headBase;
    const float* Vg = g_V + headBase;

    {
        const int r0 = tid >> 4;
        const int d0 = (tid & 15) * 4;
#pragma unroll
        for (int r = 0; r < 4; r++) {
            const int row = r0 + r * 16;
            float4 v = *(const float4*)(Qg + (size_t)(qt * 64 + row) * HDIM + d0);
            QS(d0 + 0, row) = v.x;
            QS(d0 + 1, row) = v.y;
            QS(d0 + 2, row) = v.z;
            QS(d0 + 3, row) = v.w;
        }
    }
    if (tid < 64) { mrow[tid] = -1e30f; lrow[tid] = 0.0f; }

    float o[4][4];
#pragma unroll
    for (int i = 0; i < 4; i++)
#pragma unroll
        for (int j = 0; j < 4; j++) o[i][j] = 0.0f;

    const float scale = 0.125f;

    for (int jt = 0; jt <= qt; jt++) {
        __syncthreads();

        {
            const int r0 = tid >> 4;
            const int d0 = (tid & 15) * 4;
#pragma unroll
            for (int r = 0; r < 4; r++) {
                const int row = r0 + r * 16;
                float4 kv = *(const float4*)(Kg + (size_t)(jt * 64 + row) * HDIM + d0);
                KS(d0 + 0, row) = kv.x;
                KS(d0 + 1, row) = kv.y;
                KS(d0 + 2, row) = kv.z;
                KS(d0 + 3, row) = kv.w;
                float4 vv = *(const float4*)(Vg + (size_t)(jt * 64 + row) * HDIM + d0);
                *(float4*)&VS(row, d0) = vv;
            }
        }
        __syncthreads();

        float s[4][4];
#pragma unroll
        for (int i = 0; i < 4; i++)
#pragma unroll
            for (int j = 0; j < 4; j++) s[i][j] = 0.0f;

#pragma unroll 8
        for (int d = 0; d < 64; d++) {
            float qa[4], ka[4];
#pragma unroll
            for (int i = 0; i < 4; i++) qa[i] = QS(d, ty * 4 + i);
#pragma unroll
            for (int j = 0; j < 4; j++) ka[j] = KS(d, tx * 4 + j);
#pragma unroll
            for (int i = 0; i < 4; i++)
#pragma unroll
                for (int j = 0; j < 4; j++)
                    s[i][j] = fmaf(qa[i], ka[j], s[i][j]);
        }

#pragma unroll
        for (int i = 0; i < 4; i++)
#pragma unroll
            for (int j = 0; j < 4; j++) s[i][j] *= scale;

        if (jt == qt) {
#pragma unroll
            for (int i = 0; i < 4; i++) {
                const int row = ty * 4 + i;
#pragma unroll
                for (int j = 0; j < 4; j++) {
                    const int col = tx * 4 + j;
                    if (col > row) s[i][j] = -1e30f;
                }
            }
        }

        float p[4][4];
        float corr[4];
#pragma unroll
        for (int i = 0; i < 4; i++) {
            float rm = fmaxf(fmaxf(s[i][0], s[i][1]), fmaxf(s[i][2], s[i][3]));
#pragma unroll
            for (int off = 1; off < 16; off <<= 1)
                rm = fmaxf(rm, __shfl_xor_sync(0xffffffffu, rm, off));

            const int row = ty * 4 + i;
            const float mo = mrow[row];
            const float mn = fmaxf(mo, rm);
            corr[i] = __expf(mo - mn);

            float sum = 0.0f;
#pragma unroll
            for (int j = 0; j < 4; j++) {
                const float pv = __expf(s[i][j] - mn);
                p[i][j] = pv;
                sum += pv;
            }
#pragma unroll
            for (int off = 1; off < 16; off <<= 1)
                sum += __shfl_xor_sync(0xffffffffu, sum, off);

            if (tx == 0) {
                mrow[row] = mn;
                lrow[row] = lrow[row] * corr[i] + sum;
            }
        }

#pragma unroll
        for (int i = 0; i < 4; i++)
#pragma unroll
            for (int j = 0; j < 4; j++) o[i][j] *= corr[i];

#pragma unroll
        for (int i = 0; i < 4; i++)
#pragma unroll
            for (int j = 0; j < 4; j++)
                PS(tx * 4 + j, ty * 4 + i) = p[i][j];

        __syncthreads();

#pragma unroll 4
        for (int j = 0; j < 64; j++) {
            float pb[4];
#pragma unroll
            for (int i = 0; i < 4; i++) pb[i] = PS(j, ty * 4 + i);
            float4 vv = *(const float4*)&VS(j, tx * 4);
#pragma unroll
            for (int i = 0; i < 4; i++) {
                o[i][0] = fmaf(pb[i], vv.x, o[i][0]);
                o[i][1] = fmaf(pb[i], vv.y, o[i][1]);
                o[i][2] = fmaf(pb[i], vv.z, o[i][2]);
                o[i][3] = fmaf(pb[i], vv.w, o[i][3]);
            }
        }
    }

#pragma unroll
    for (int i = 0; i < 4; i++) {
        const int row = ty * 4 + i;
        const float inv = 1.0f / lrow[row];
        const int t = qt * 64 + row;
        float4 ov;
        ov.x = o[i][0] * inv;
        ov.y = o[i][1] * inv;
        ov.z = o[i][2] * inv;
        ov.w = o[i][3] * inv;
        *(float4*)&g_Y[((size_t)b * SEQ + t) * CDIM + h * HDIM + tx * 4] = ov;
    }
}

// ---------------------------------------------------------------------------
// Launch
// ---------------------------------------------------------------------------
extern "C" void kernel_launch(void* const* d_in, const int* in_sizes, int n_in,
                              void* d_out, int out_size)
{
    const float* x  = (const float*)d_in[0];
    const float* Wq = (const float*)d_in[1];
    const float* bq = (const float*)d_in[2];
    const float* Wk = (const float*)d_in[3];
    const float* bk = (const float*)d_in[4];
    const float* Wv = (const float*)d_in[5];
    const float* bv = (const float*)d_in[6];
    const float* Wp = (const float*)d_in[7];
    const float* bp = (const float*)d_in[8];

    float *Qp, *Kp, *Vp, *Yp;
    __nv_bfloat16 *A3p, *Y3p, *W3qp, *W3kp, *W3vp, *W3pp;
    cudaGetSymbolAddress((void**)&Qp, g_Q);
    cudaGetSymbolAddress((void**)&Kp, g_K);
    cudaGetSymbolAddress((void**)&Vp, g_V);
    cudaGetSymbolAddress((void**)&Yp, g_Y);
    cudaGetSymbolAddress((void**)&A3p, g_A3);
    cudaGetSymbolAddress((void**)&Y3p, g_Y3);
    cudaGetSymbolAddress((void**)&W3qp, g_W3q);
    cudaGetSymbolAddress((void**)&W3kp, g_W3k);
    cudaGetSymbolAddress((void**)&W3vp, g_W3v);
    cudaGetSymbolAddress((void**)&W3pp, g_W3p);

    cudaFuncSetAttribute(flash_attn_kernel,
                         cudaFuncAttributeMaxDynamicSharedMemorySize,
                         ATT_SMEM_BYTES);

    // Split-convert activations and weights
    const int actTotal = MROWS * CDIM;     // 8.4M
    const int wTotal   = CDIM * CDIM;      // 1.05M
    cvt_split3<<<(actTotal + 255) / 256, 256>>>(x, A3p, actTotal, 1);
    cvt_split3<<<(wTotal + 255) / 256, 256>>>(Wq, W3qp, wTotal, 0);
    cvt_split3<<<(wTotal + 255) / 256, 256>>>(Wk, W3kp, wTotal, 0);
    cvt_split3<<<(wTotal + 255) / 256, 256>>>(Wv, W3vp, wTotal, 0);
    cvt_split3<<<(wTotal + 255) / 256, 256>>>(Wp, W3pp, wTotal, 0);

    // QKV projections on tensor cores
    dim3 gemmGrid(CDIM / 128, MROWS / 128);   // (8, 64)
    gemm_bf16_mma<<<gemmGrid, 256>>>(A3p, W3qp, bq, Qp, 0);
    gemm_bf16_mma<<<gemmGrid, 256>>>(A3p, W3kp, bk, Kp, 0);
    gemm_bf16_mma<<<gemmGrid, 256>>>(A3p, W3vp, bv, Vp, 0);

    // Attention (fp32, unchanged)
    dim3 attnGrid(SEQ / 64, NHEAD, BATCH);    // (32, 16, 4)
    flash_attn_kernel<<<attnGrid, 256, ATT_SMEM_BYTES>>>();

    // Output projection on tensor cores
    cvt_split3<<<(actTotal + 255) / 256, 256>>>(Yp, Y3p, actTotal, 1);
    gemm_bf16_mma<<<gemmGrid, 256>>>(Y3p, W3pp, bp, (float*)d_out, 1);
}

// round 7
// speedup vs baseline: 2.5265x; 1.5643x over previous
#include <cuda_runtime.h>
#include <cuda_bf16.h>
#include <cstdint>

// Problem constants (fixed by setup_inputs)
#define BATCH 4
#define SEQ   2048
#define CDIM  1024
#define NHEAD 16
#define HDIM  64
#define MROWS (BATCH * SEQ)   // 8192
#define K3    (3 * CDIM)      // 3072 : [hi | hi | lo] x [hi | lo | hi]

// Scratch (allocation-free: __device__ globals)
__device__ __nv_bfloat16 g_A3[MROWS * K3];   // split-expanded x
__device__ __nv_bfloat16 g_Y3[MROWS * K3];   // split-expanded attention output
__device__ __nv_bfloat16 g_W3q[CDIM * K3];
__device__ __nv_bfloat16 g_W3k[CDIM * K3];
__device__ __nv_bfloat16 g_W3v[CDIM * K3];
__device__ __nv_bfloat16 g_W3p[CDIM * K3];

// bf16 hi/lo split Q,K in [B,H,T,D]; V transposed in [B,H,D,T]
__device__ __nv_bfloat16 g_Qhi[BATCH * NHEAD * SEQ * HDIM];
__device__ __nv_bfloat16 g_Qlo[BATCH * NHEAD * SEQ * HDIM];
__device__ __nv_bfloat16 g_Khi[BATCH * NHEAD * SEQ * HDIM];
__device__ __nv_bfloat16 g_Klo[BATCH * NHEAD * SEQ * HDIM];
__device__ __nv_bfloat16 g_VThi[BATCH * NHEAD * HDIM * SEQ];
__device__ __nv_bfloat16 g_VTlo[BATCH * NHEAD * HDIM * SEQ];

// ---------------------------------------------------------------------------
// Split-convert: fp32 [rows,1024] -> bf16 [rows,3072].
// modeA=1: [hi | hi | lo] (activations), modeA=0: [hi | lo | hi] (weights)
// ---------------------------------------------------------------------------
__global__ __launch_bounds__(256)
void cvt_split3(const float* __restrict__ src, __nv_bfloat16* __restrict__ dst,
                int total, int modeA)
{
    int idx = blockIdx.x * 256 + threadIdx.x;
    if (idx >= total) return;
    int r = idx >> 10;
    int k = idx & 1023;
    float a = src[idx];
    __nv_bfloat16 hi = __float2bfloat16(a);
    __nv_bfloat16 lo = __float2bfloat16(a - __bfloat162float(hi));
    __nv_bfloat16* row = dst + (size_t)r * K3;
    if (modeA) {
        row[k]        = hi;
        row[k + 1024] = hi;
        row[k + 2048] = lo;
    } else {
        row[k]        = hi;
        row[k + 1024] = lo;
        row[k + 2048] = hi;
    }
}

// ---------------------------------------------------------------------------
// mma.sync m16n8k16 bf16 -> fp32
// ---------------------------------------------------------------------------
__device__ __forceinline__ void mma16816(float* d, const uint32_t* a, const uint32_t* b)
{
    asm volatile(
        "mma.sync.aligned.m16n8k16.row.col.f32.bf16.bf16.f32 "
        "{%0,%1,%2,%3}, {%4,%5,%6,%7}, {%8,%9}, {%0,%1,%2,%3};"
        : "+f"(d[0]), "+f"(d[1]), "+f"(d[2]), "+f"(d[3])
        : "r"(a[0]), "r"(a[1]), "r"(a[2]), "r"(a[3]),
          "r"(b[0]), "r"(b[1]));
}

__device__ __forceinline__ uint32_t pack2bf(float a, float b)
{
    __nv_bfloat162 h = __floats2bfloat162_rn(a, b);
    return *(uint32_t*)&h;
}

__device__ __forceinline__ void hilo2(float a, float b, uint32_t& hi, uint32_t& lo)
{
    __nv_bfloat16 ha = __float2bfloat16(a);
    __nv_bfloat16 hb = __float2bfloat16(b);
    __nv_bfloat16 la = __float2bfloat16(a - __bfloat162float(ha));
    __nv_bfloat16 lb = __float2bfloat16(b - __bfloat162float(hb));
    __nv_bfloat162 hh; hh.x = ha; hh.y = hb;
    __nv_bfloat162 ll; ll.x = la; ll.y = lb;
    hi = *(uint32_t*)&hh;
    lo = *(uint32_t*)&ll;
}

// ---------------------------------------------------------------------------
// bf16 tensor-core GEMM: out[M,1024] = A3[M,3072] @ W3[1024,3072]^T + bias.
// mode 0: bf16 hi/lo split-heads [B,H,T,D] (Q/K)
// mode 2: bf16 hi/lo transposed heads [B,H,D,T] (V)
// mode 1: fp32 plain [M,N] (final output)
// ---------------------------------------------------------------------------
#define SMPAD 40   // padded row length in bf16 elements

__global__ __launch_bounds__(256)
void gemm_bf16_mma(const __nv_bfloat16* __restrict__ A,
                   const __nv_bfloat16* __restrict__ W,
                   const float* __restrict__ bias,
                   float* __restrict__ outF,
                   __nv_bfloat16* __restrict__ outH,
                   __nv_bfloat16* __restrict__ outL,
                   int mode)
{
    __shared__ __nv_bfloat16 As[128][SMPAD];
    __shared__ __nv_bfloat16 Ws[128][SMPAD];

    const int tid  = threadIdx.x;
    const int bm   = blockIdx.y * 128;
    const int bn   = blockIdx.x * 128;
    const int warp = tid >> 5;
    const int lane = tid & 31;
    const int wm   = (warp >> 2) * 64;
    const int wn   = (warp & 3) * 32;
    const int g    = lane >> 2;
    const int c    = lane & 3;

    const int r0 = tid >> 2,         q0 = tid & 3;
    const int r1 = (tid + 256) >> 2, q1 = (tid + 256) & 3;

    const __nv_bfloat16* Ag0 = A + (size_t)(bm + r0) * K3 + q0 * 8;
    const __nv_bfloat16* Ag1 = A + (size_t)(bm + r1) * K3 + q1 * 8;
    const __nv_bfloat16* Wg0 = W + (size_t)(bn + r0) * K3 + q0 * 8;
    const __nv_bfloat16* Wg1 = W + (size_t)(bn + r1) * K3 + q1 * 8;

    float acc[4][4][4];
#pragma unroll
    for (int i = 0; i < 4; i++)
#pragma unroll
        for (int j = 0; j < 4; j++)
#pragma unroll
            for (int e = 0; e < 4; e++) acc[i][j][e] = 0.0f;

    uint4 pa0 = *(const uint4*)(Ag0);
    uint4 pa1 = *(const uint4*)(Ag1);
    uint4 pw0 = *(const uint4*)(Wg0);
    uint4 pw1 = *(const uint4*)(Wg1);

    for (int k0 = 0; k0 < K3; k0 += 32) {
        *(uint4*)&As[r0][q0 * 8] = pa0;
        *(uint4*)&As[r1][q1 * 8] = pa1;
        *(uint4*)&Ws[r0][q0 * 8] = pw0;
        *(uint4*)&Ws[r1][q1 * 8] = pw1;
        __syncthreads();

        if (k0 + 32 < K3) {
            pa0 = *(const uint4*)(Ag0 + k0 + 32);
            pa1 = *(const uint4*)(Ag1 + k0 + 32);
            pw0 = *(const uint4*)(Wg0 + k0 + 32);
            pw1 = *(const uint4*)(Wg1 + k0 + 32);
        }

#pragma unroll
        for (int kk = 0; kk < 2; kk++) {
            const int kb = kk * 16;
            uint32_t af[4][4];
#pragma unroll
            for (int mf = 0; mf < 4; mf++) {
                const int mr = wm + mf * 16 + g;
                af[mf][0] = *(const uint32_t*)&As[mr    ][kb + 2 * c];
                af[mf][1] = *(const uint32_t*)&As[mr + 8][kb + 2 * c];
                af[mf][2] = *(const uint32_t*)&As[mr    ][kb + 2 * c + 8];
                af[mf][3] = *(const uint32_t*)&As[mr + 8][kb + 2 * c + 8];
            }
            uint32_t bf[4][2];
#pragma unroll
            for (int nf = 0; nf < 4; nf++) {
                const int nr = wn + nf * 8 + g;
                bf[nf][0] = *(const uint32_t*)&Ws[nr][kb + 2 * c];
                bf[nf][1] = *(const uint32_t*)&Ws[nr][kb + 2 * c + 8];
            }
#pragma unroll
            for (int mf = 0; mf < 4; mf++)
#pragma unroll
                for (int nf = 0; nf < 4; nf++)
                    mma16816(acc[mf][nf], af[mf], bf[nf]);
        }
        __syncthreads();
    }

#pragma unroll
    for (int nf = 0; nf < 4; nf++) {
        const int col = bn + wn + nf * 8 + 2 * c;
        const float b0 = bias[col];
        const float b1 = bias[col + 1];
#pragma unroll
        for (int mf = 0; mf < 4; mf++) {
            const int row = bm + wm + mf * 16 + g;
            const float v00 = acc[mf][nf][0] + b0;
            const float v01 = acc[mf][nf][1] + b1;
            const float v10 = acc[mf][nf][2] + b0;
            const float v11 = acc[mf][nf][3] + b1;
            if (mode == 1) {
                *(float2*)(outF + (size_t)row * CDIM + col)       = make_float2(v00, v01);
                *(float2*)(outF + (size_t)(row + 8) * CDIM + col) = make_float2(v10, v11);
            } else {
                const int h  = col >> 6;
                const int d  = col & (HDIM - 1);
                const int b_ = row >> 11;
                const int t0 = row & (SEQ - 1);
                const int t1 = (row + 8) & (SEQ - 1);
                uint32_t h0, l0, h1, l1;
                hilo2(v00, v01, h0, l0);
                hilo2(v10, v11, h1, l1);
                if (mode == 0) {
                    // [B,H,T,D]
                    const size_t i0 = ((size_t)(b_ * NHEAD + h) * SEQ + t0) * HDIM + d;
                    const size_t i1 = ((size_t)(b_ * NHEAD + h) * SEQ + t1) * HDIM + d;
                    *(uint32_t*)&outH[i0] = h0;
                    *(uint32_t*)&outL[i0] = l0;
                    *(uint32_t*)&outH[i1] = h1;
                    *(uint32_t*)&outL[i1] = l1;
                } else {
                    // mode 2: [B,H,D,T] (transposed V)
                    const size_t base = ((size_t)(b_ * NHEAD + h) * HDIM + d) * SEQ;
                    __nv_bfloat162 hh0 = *(__nv_bfloat162*)&h0;
                    __nv_bfloat162 ll0 = *(__nv_bfloat162*)&l0;
                    __nv_bfloat162 hh1 = *(__nv_bfloat162*)&h1;
                    __nv_bfloat162 ll1 = *(__nv_bfloat162*)&l1;
                    outH[base + t0]       = hh0.x;
                    outH[base + SEQ + t0] = hh0.y;
                    outH[base + t1]       = hh1.x;
                    outH[base + SEQ + t1] = hh1.y;
                    outL[base + t0]       = ll0.x;
                    outL[base + SEQ + t0] = ll0.y;
                    outL[base + t1]       = ll1.x;
                    outL[base + SEQ + t1] = ll1.y;
                }
            }
        }
    }
}

// ---------------------------------------------------------------------------
// Flash attention (causal) on tensor cores with 3-term bf16 compensation.
// BQ=128, BK=64, 8 warps; warp w owns q-rows [16w,16w+16) exclusively.
// S = Qhi*Khi + Qhi*Klo + Qlo*Khi ; O += Phi*Vhi + Phi*Vlo + Plo*Vhi
// P fragments built in registers from S accumulators (no smem round-trip).
// Writes split-expanded Y3 [hi|hi|lo] directly.
// ---------------------------------------------------------------------------
#define AST 72   // padded smem row stride (bf16 elems)
#define ATT_SMEM_BYTES ((2 * 128 * AST + 4 * 64 * AST) * 2)   // 73728 B

__global__ __launch_bounds__(256)
void flash_attn_mma(__nv_bfloat16* __restrict__ Y3)
{
    extern __shared__ __nv_bfloat16 smem[];
    __nv_bfloat16* Qh = smem;                 // 128 x AST
    __nv_bfloat16* Ql = Qh + 128 * AST;
    __nv_bfloat16* Kh = Ql + 128 * AST;       // 64 x AST
    __nv_bfloat16* Kl = Kh + 64 * AST;
    __nv_bfloat16* Vh = Kl + 64 * AST;        // VT: 64 x AST
    __nv_bfloat16* Vl = Vh + 64 * AST;

    const int qt  = blockIdx.x;   // 0..15
    const int h   = blockIdx.y;
    const int b   = blockIdx.z;
    const int tid = threadIdx.x;
    const int warp = tid >> 5;
    const int lane = tid & 31;
    const int g    = lane >> 2;
    const int c    = lane & 3;
    const int qrl  = warp * 16;               // local q-row base of this warp

    const size_t headBase = (size_t)(b * NHEAD + h) * SEQ * HDIM;
    const __nv_bfloat16* qh_g = g_Qhi + headBase + (size_t)qt * 128 * HDIM;
    const __nv_bfloat16* ql_g = g_Qlo + headBase + (size_t)qt * 128 * HDIM;
    const __nv_bfloat16* kh_g = g_Khi + headBase;
    const __nv_bfloat16* kl_g = g_Klo + headBase;
    const __nv_bfloat16* vh_g = g_VThi + headBase;   // [D,T] within head
    const __nv_bfloat16* vl_g = g_VTlo + headBase;

    // Load Q tile (128 x 64 hi + lo)
    {
        const int row = tid >> 1;
        const int d0  = (tid & 1) * 32;
#pragma unroll
        for (int i = 0; i < 4; i++) {
            *(uint4*)&Qh[row * AST + d0 + i * 8] =
                *(const uint4*)(qh_g + (size_t)row * HDIM + d0 + i * 8);
            *(uint4*)&Ql[row * AST + d0 + i * 8] =
                *(const uint4*)(ql_g + (size_t)row * HDIM + d0 + i * 8);
        }
    }

    float oacc[8][4];
#pragma unroll
    for (int n = 0; n < 8; n++)
#pragma unroll
        for (int e = 0; e < 4; e++) oacc[n][e] = 0.0f;

    float m0 = -1e30f, m1 = -1e30f, l0 = 0.0f, l1 = 0.0f;
    const float SC = 0.125f;   // 1/sqrt(64)
    const int tw = qt * 128 + qrl;           // global first row of warp
    const int warpRowMax = tw + 15;
    const int jtEnd = 2 * qt + 1;

    for (int jt = 0; jt <= jtEnd; jt++) {
        __syncthreads();
        // Load K (hi/lo) [64 x 64] and VT (hi/lo) [64 x 64]
        {
            const int j  = tid >> 2;
            const int d8 = (tid & 3) * 16;
            const size_t kg = (size_t)(jt * 64 + j) * HDIM;
            *(uint4*)&Kh[j * AST + d8]     = *(const uint4*)(kh_g + kg + d8);
            *(uint4*)&Kh[j * AST + d8 + 8] = *(const uint4*)(kh_g + kg + d8 + 8);
            *(uint4*)&Kl[j * AST + d8]     = *(const uint4*)(kl_g + kg + d8);
            *(uint4*)&Kl[j * AST + d8 + 8] = *(const uint4*)(kl_g + kg + d8 + 8);
            const size_t vg = (size_t)j * SEQ + jt * 64;   // row j = channel d here
            *(uint4*)&Vh[j * AST + d8]     = *(const uint4*)(vh_g + vg + d8);
            *(uint4*)&Vh[j * AST + d8 + 8] = *(const uint4*)(vh_g + vg + d8 + 8);
            *(uint4*)&Vl[j * AST + d8]     = *(const uint4*)(vl_g + vg + d8);
            *(uint4*)&Vl[j * AST + d8 + 8] = *(const uint4*)(vl_g + vg + d8 + 8);
        }
        __syncthreads();

        if (jt * 64 > warpRowMax) continue;   // fully masked for this warp

        // ----- S = Q K^T (3-term) -----
        float sacc[8][4];
#pragma unroll
        for (int n = 0; n < 8; n++)
#pragma unroll
            for (int e = 0; e < 4; e++) sacc[n][e] = 0.0f;

#pragma unroll
        for (int s = 0; s < 4; s++) {
            uint32_t qhf[4], qlf[4];
            qhf[0] = *(const uint32_t*)&Qh[(qrl + g)     * AST + s * 16 + 2 * c];
            qhf[1] = *(const uint32_t*)&Qh[(qrl + g + 8) * AST + s * 16 + 2 * c];
            qhf[2] = *(const uint32_t*)&Qh[(qrl + g)     * AST + s * 16 + 2 * c + 8];
            qhf[3] = *(const uint32_t*)&Qh[(qrl + g + 8) * AST + s * 16 + 2 * c + 8];
            qlf[0] = *(const uint32_t*)&Ql[(qrl + g)     * AST + s * 16 + 2 * c];
            qlf[1] = *(const uint32_t*)&Ql[(qrl + g + 8) * AST + s * 16 + 2 * c];
            qlf[2] = *(const uint32_t*)&Ql[(qrl + g)     * AST + s * 16 + 2 * c + 8];
            qlf[3] = *(const uint32_t*)&Ql[(qrl + g + 8) * AST + s * 16 + 2 * c + 8];
#pragma unroll
            for (int n = 0; n < 8; n++) {
                uint32_t bh[2], bl[2];
                bh[0] = *(const uint32_t*)&Kh[(n * 8 + g) * AST + s * 16 + 2 * c];
                bh[1] = *(const uint32_t*)&Kh[(n * 8 + g) * AST + s * 16 + 2 * c + 8];
                bl[0] = *(const uint32_t*)&Kl[(n * 8 + g) * AST + s * 16 + 2 * c];
                bl[1] = *(const uint32_t*)&Kl[(n * 8 + g) * AST + s * 16 + 2 * c + 8];
                mma16816(sacc[n], qhf, bh);
                mma16816(sacc[n], qhf, bl);
                mma16816(sacc[n], qlf, bh);
            }
        }

        // ----- causal mask (diagonal tiles only) -----
        if (jt * 64 + 63 > tw) {
            const int r0g = tw + g;
            const int r1g = tw + g + 8;
#pragma unroll
            for (int n = 0; n < 8; n++) {
                const int col = jt * 64 + n * 8 + 2 * c;
                if (col     > r0g) sacc[n][0] = -1e30f;
                if (col + 1 > r0g) sacc[n][1] = -1e30f;
                if (col     > r1g) sacc[n][2] = -1e30f;
                if (col + 1 > r1g) sacc[n][3] = -1e30f;
            }
        }

        // ----- online softmax (rows g, g+8; raw-scale max tracking) -----
        float mx0 = -1e30f, mx1 = -1e30f;
#pragma unroll
        for (int n = 0; n < 8; n++) {
            mx0 = fmaxf(mx0, fmaxf(sacc[n][0], sacc[n][1]));
            mx1 = fmaxf(mx1, fmaxf(sacc[n][2], sacc[n][3]));
        }
        mx0 = fmaxf(mx0, __shfl_xor_sync(0xffffffffu, mx0, 1));
        mx0 = fmaxf(mx0, __shfl_xor_sync(0xffffffffu, mx0, 2));
        mx1 = fmaxf(mx1, __shfl_xor_sync(0xffffffffu, mx1, 1));
        mx1 = fmaxf(mx1, __shfl_xor_sync(0xffffffffu, mx1, 2));

        const float m0n = fmaxf(m0, mx0);
        const float m1n = fmaxf(m1, mx1);
        const float corr0 = __expf((m0 - m0n) * SC);
        const float corr1 = __expf((m1 - m1n) * SC);

        float sum0 = 0.0f, sum1 = 0.0f;
#pragma unroll
        for (int n = 0; n < 8; n++) {
            sacc[n][0] = __expf((sacc[n][0] - m0n) * SC);
            sacc[n][1] = __expf((sacc[n][1] - m0n) * SC);
            sacc[n][2] = __expf((sacc[n][2] - m1n) * SC);
            sacc[n][3] = __expf((sacc[n][3] - m1n) * SC);
            sum0 += sacc[n][0] + sacc[n][1];
            sum1 += sacc[n][2] + sacc[n][3];
        }
        sum0 += __shfl_xor_sync(0xffffffffu, sum0, 1);
        sum0 += __shfl_xor_sync(0xffffffffu, sum0, 2);
        sum1 += __shfl_xor_sync(0xffffffffu, sum1, 1);
        sum1 += __shfl_xor_sync(0xffffffffu, sum1, 2);

        l0 = l0 * corr0 + sum0;
        l1 = l1 * corr1 + sum1;
        m0 = m0n;
        m1 = m1n;

#pragma unroll
        for (int n = 0; n < 8; n++) {
            oacc[n][0] *= corr0;
            oacc[n][1] *= corr0;
            oacc[n][2] *= corr1;
            oacc[n][3] *= corr1;
        }

        // ----- O += P V (3-term); P frags from S accumulators -----
#pragma unroll
        for (int s = 0; s < 4; s++) {
            uint32_t ah[4], al[4];
            hilo2(sacc[2 * s][0],     sacc[2 * s][1],     ah[0], al[0]);
            hilo2(sacc[2 * s][2],     sacc[2 * s][3],     ah[1], al[1]);
            hilo2(sacc[2 * s + 1][0], sacc[2 * s + 1][1], ah[2], al[2]);
            hilo2(sacc[2 * s + 1][2], sacc[2 * s + 1][3], ah[3], al[3]);
#pragma unroll
            for (int n = 0; n < 8; n++) {
                uint32_t bh[2], bl[2];
                bh[0] = *(const uint32_t*)&Vh[(n * 8 + g) * AST + s * 16 + 2 * c];
                bh[1] = *(const uint32_t*)&Vh[(n * 8 + g) * AST + s * 16 + 2 * c + 8];
                bl[0] = *(const uint32_t*)&Vl[(n * 8 + g) * AST + s * 16 + 2 * c];
                bl[1] = *(const uint32_t*)&Vl[(n * 8 + g) * AST + s * 16 + 2 * c + 8];
                mma16816(oacc[n], ah, bh);
                mma16816(oacc[n], ah, bl);
                mma16816(oacc[n], al, bh);
            }
        }
    }

    // ----- epilogue: normalize, write split-expanded Y3 [hi|hi|lo] -----
    const float inv0 = 1.0f / l0;
    const float inv1 = 1.0f / l1;
    const int t0 = qt * 128 + qrl + g;
    const int t1 = t0 + 8;
    const size_t r0 = (size_t)(b * SEQ + t0) * K3;
    const size_t r1 = (size_t)(b * SEQ + t1) * K3;
    const int ch = h * HDIM;
#pragma unroll
    for (int n = 0; n < 8; n++) {
        const int col = ch + n * 8 + 2 * c;
        uint32_t h0, l0p, h1, l1p;
        hilo2(oacc[n][0] * inv0, oacc[n][1] * inv0, h0, l0p);
        hilo2(oacc[n][2] * inv1, oacc[n][3] * inv1, h1, l1p);
        *(uint32_t*)&Y3[r0 + col]        = h0;
        *(uint32_t*)&Y3[r0 + 1024 + col] = h0;
        *(uint32_t*)&Y3[r0 + 2048 + col] = l0p;
        *(uint32_t*)&Y3[r1 + col]        = h1;
        *(uint32_t*)&Y3[r1 + 1024 + col] = h1;
        *(uint32_t*)&Y3[r1 + 2048 + col] = l1p;
    }
}

// ---------------------------------------------------------------------------
// Launch
// ---------------------------------------------------------------------------
extern "C" void kernel_launch(void* const* d_in, const int* in_sizes, int n_in,
                              void* d_out, int out_size)
{
    const float* x  = (const float*)d_in[0];
    const float* Wq = (const float*)d_in[1];
    const float* bq = (const float*)d_in[2];
    const float* Wk = (const float*)d_in[3];
    const float* bk = (const float*)d_in[4];
    const float* Wv = (const float*)d_in[5];
    const float* bv = (const float*)d_in[6];
    const float* Wp = (const float*)d_in[7];
    const float* bp = (const float*)d_in[8];

    __nv_bfloat16 *A3p, *Y3p, *W3qp, *W3kp, *W3vp, *W3pp;
    __nv_bfloat16 *Qhip, *Qlop, *Khip, *Klop, *VThip, *VTlop;
    cudaGetSymbolAddress((void**)&A3p, g_A3);
    cudaGetSymbolAddress((void**)&Y3p, g_Y3);
    cudaGetSymbolAddress((void**)&W3qp, g_W3q);
    cudaGetSymbolAddress((void**)&W3kp, g_W3k);
    cudaGetSymbolAddress((void**)&W3vp, g_W3v);
    cudaGetSymbolAddress((void**)&W3pp, g_W3p);
    cudaGetSymbolAddress((void**)&Qhip, g_Qhi);
    cudaGetSymbolAddress((void**)&Qlop, g_Qlo);
    cudaGetSymbolAddress((void**)&Khip, g_Khi);
    cudaGetSymbolAddress((void**)&Klop, g_Klo);
    cudaGetSymbolAddress((void**)&VThip, g_VThi);
    cudaGetSymbolAddress((void**)&VTlop, g_VTlo);

    cudaFuncSetAttribute(flash_attn_mma,
                         cudaFuncAttributeMaxDynamicSharedMemorySize,
                         ATT_SMEM_BYTES);

    const int actTotal = MROWS * CDIM;
    const int wTotal   = CDIM * CDIM;
    cvt_split3<<<(actTotal + 255) / 256, 256>>>(x, A3p, actTotal, 1);
    cvt_split3<<<(wTotal + 255) / 256, 256>>>(Wq, W3qp, wTotal, 0);
    cvt_split3<<<(wTotal + 255) / 256, 256>>>(Wk, W3kp, wTotal, 0);
    cvt_split3<<<(wTotal + 255) / 256, 256>>>(Wv, W3vp, wTotal, 0);
    cvt_split3<<<(wTotal + 255) / 256, 256>>>(Wp, W3pp, wTotal, 0);

    dim3 gemmGrid(CDIM / 128, MROWS / 128);   // (8, 64)
    gemm_bf16_mma<<<gemmGrid, 256>>>(A3p, W3qp, bq, nullptr, Qhip, Qlop, 0);
    gemm_bf16_mma<<<gemmGrid, 256>>>(A3p, W3kp, bk, nullptr, Khip, Klop, 0);
    gemm_bf16_mma<<<gemmGrid, 256>>>(A3p, W3vp, bv, nullptr, VThip, VTlop, 2);

    dim3 attnGrid(SEQ / 128, NHEAD, BATCH);   // (16, 16, 4)
    flash_attn_mma<<<attnGrid, 256, ATT_SMEM_BYTES>>>(Y3p);

    gemm_bf16_mma<<<gemmGrid, 256>>>(Y3p, W3pp, bp, (float*)d_out, nullptr, nullptr, 1);
}